// round 1
// baseline (speedup 1.0000x reference)
#include <cuda_runtime.h>
#include <math.h>

// Problem constants
#define BDIM   2
#define LDIM   2048
#define DMODEL 1024
#define HEADS  16
#define DKH    64
#define D3     (3 * DMODEL)
#define ROWS   (BDIM * LDIM)   // 4096

// Scratch (allocation-free: __device__ globals)
__device__ float g_qkv[(size_t)ROWS * D3];      // [B*L, 3*D] = [B,L,3,H,dk]
__device__ float g_attn[(size_t)ROWS * DMODEL]; // [B,L,H,dk]

// ---------------------------------------------------------------------------
// Tiled SGEMM with bias: C[M,N] = A[M,K] @ B[K,N] + bias[N]
// 128x128 tile, K-step 8, 256 threads, 8x8 microtile per thread.
// Requires M%128==0, N%128==0, K%8==0 (true for all our shapes).
// ---------------------------------------------------------------------------
__global__ __launch_bounds__(256) void sgemm_bias_kernel(
    const float* __restrict__ A, const float* __restrict__ B,
    const float* __restrict__ bias, float* __restrict__ C,
    int M, int N, int K)
{
    __shared__ float As[8][128];
    __shared__ float Bs[8][128];

    const int tid = threadIdx.x;
    const int tx  = tid & 15;   // column group (8 cols each)
    const int ty  = tid >> 4;   // row group (8 rows each)
    const int m0  = blockIdx.y * 128;
    const int n0  = blockIdx.x * 128;

    // A-tile load mapping: 128 rows x 8 cols, each thread: one float4
    const int ar = tid >> 1;          // 0..127
    const int ak = (tid & 1) * 4;     // 0 or 4
    // B-tile load mapping: 8 rows x 128 cols, each thread: one float4
    const int br = tid >> 5;          // 0..7
    const int bc = (tid & 31) * 4;    // 0..124

    const float* Aptr = A + (size_t)(m0 + ar) * K + ak;
    const float* Bptr = B + (size_t)br * N + n0 + bc;

    float acc[8][8];
    #pragma unroll
    for (int i = 0; i < 8; i++)
        #pragma unroll
        for (int j = 0; j < 8; j++)
            acc[i][j] = 0.0f;

    for (int k0 = 0; k0 < K; k0 += 8) {
        float4 av = *(const float4*)(Aptr + k0);
        float4 bv = *(const float4*)(Bptr + (size_t)k0 * N);
        As[ak + 0][ar] = av.x;
        As[ak + 1][ar] = av.y;
        As[ak + 2][ar] = av.z;
        As[ak + 3][ar] = av.w;
        *(float4*)&Bs[br][bc] = bv;
        __syncthreads();

        #pragma unroll
        for (int kk = 0; kk < 8; kk++) {
            float a[8], b[8];
            *(float4*)&a[0] = *(const float4*)&As[kk][ty * 8];
            *(float4*)&a[4] = *(const float4*)&As[kk][ty * 8 + 4];
            *(float4*)&b[0] = *(const float4*)&Bs[kk][tx * 8];
            *(float4*)&b[4] = *(const float4*)&Bs[kk][tx * 8 + 4];
            #pragma unroll
            for (int i = 0; i < 8; i++)
                #pragma unroll
                for (int j = 0; j < 8; j++)
                    acc[i][j] += a[i] * b[j];
        }
        __syncthreads();
    }

    // Epilogue with bias
    #pragma unroll
    for (int i = 0; i < 8; i++) {
        size_t row = (size_t)(m0 + ty * 8 + i);
        #pragma unroll
        for (int j = 0; j < 8; j += 4) {
            int col = n0 + tx * 8 + j;
            float4 v;
            v.x = acc[i][j + 0] + bias[col + 0];
            v.y = acc[i][j + 1] + bias[col + 1];
            v.z = acc[i][j + 2] + bias[col + 2];
            v.w = acc[i][j + 3] + bias[col + 3];
            *(float4*)&C[row * N + col] = v;
        }
    }
}

// ---------------------------------------------------------------------------
// Flash-attention style fused kernel.
// Grid: (L/64, B*H). Block: 256 threads = 16x16; each thread owns a 4x4 tile.
// qkv layout: [B, L, 3, H, dk]  (row-major flat of [B*L, 3*D])
// out layout: [B, L, H, dk]
// ---------------------------------------------------------------------------
#define BQ 64
#define BK 64
#define KT_STRIDE 68   // padded d-major K tile; 68*4B = 272B, 16B-aligned rows

// smem plan (floats): Qs 64*64 | Kts 64*68 | Vs 64*64 | Ps 64*64 | ms 64 ints
#define SM_QS   0
#define SM_KT   (SM_QS + 64 * 64)
#define SM_VS   (SM_KT + 64 * KT_STRIDE)
#define SM_PS   (SM_VS + 64 * 64)
#define SM_MS   (SM_PS + 64 * 64)
#define ATTN_SMEM_BYTES ((SM_MS + 64) * 4)

__global__ __launch_bounds__(256) void attn_kernel(
    const float* __restrict__ qkv, const int* __restrict__ mask,
    float* __restrict__ out)
{
    extern __shared__ float sm[];
    float* Qs  = sm + SM_QS;
    float* Kts = sm + SM_KT;
    float* Vs  = sm + SM_VS;
    float* Ps  = sm + SM_PS;
    int*   ms  = (int*)(sm + SM_MS);

    const int tid = threadIdx.x;
    const int tx  = tid & 15;
    const int ty  = tid >> 4;
    const int bh  = blockIdx.y;
    const int b   = bh >> 4;
    const int h   = bh & 15;
    const int q0  = blockIdx.x * BQ;
    const float scale = 0.125f;  // 1/sqrt(64)

    // base element offset for (b, l=0, s=0, h, d=0); l-stride = 3072, s-stride = 1024
    const size_t base = (size_t)b * LDIM * D3 + (size_t)h * DKH;

    // Load Q tile (row-major [r][d]), coalesced float4
    for (int i = tid; i < 64 * 16; i += 256) {
        int r  = i >> 4;
        int d4 = (i & 15) * 4;
        float4 v = *(const float4*)&qkv[base + (size_t)(q0 + r) * D3 + d4];
        *(float4*)&Qs[r * 64 + d4] = v;
    }

    float m_i[4], l_i[4], o[4][4];
    #pragma unroll
    for (int i = 0; i < 4; i++) {
        m_i[i] = -INFINITY;
        l_i[i] = 0.0f;
        #pragma unroll
        for (int j = 0; j < 4; j++) o[i][j] = 0.0f;
    }

    for (int k0 = 0; k0 < LDIM; k0 += BK) {
        __syncthreads();  // protect previous iteration's smem reads

        // Load K (transposed to d-major, padded) and V (row-major)
        for (int i = tid; i < 64 * 16; i += 256) {
            int c  = i >> 4;
            int d4 = (i & 15) * 4;
            float4 kv = *(const float4*)&qkv[base + (size_t)(k0 + c) * D3 + DMODEL + d4];
            Kts[(d4 + 0) * KT_STRIDE + c] = kv.x;
            Kts[(d4 + 1) * KT_STRIDE + c] = kv.y;
            Kts[(d4 + 2) * KT_STRIDE + c] = kv.z;
            Kts[(d4 + 3) * KT_STRIDE + c] = kv.w;
            float4 vv = *(const float4*)&qkv[base + (size_t)(k0 + c) * D3 + 2 * DMODEL + d4];
            *(float4*)&Vs[c * 64 + d4] = vv;
        }
        if (tid < 64) ms[tid] = mask[b * LDIM + k0 + tid];
        __syncthreads();

        // S = Q @ K^T  (each thread: rows ty*4.., cols tx*4..)
        float s[4][4];
        #pragma unroll
        for (int i = 0; i < 4; i++)
            #pragma unroll
            for (int j = 0; j < 4; j++) s[i][j] = 0.0f;

        for (int d = 0; d < 64; d += 4) {
            float4 qa[4], kb[4];
            #pragma unroll
            for (int i = 0; i < 4; i++)
                qa[i] = *(const float4*)&Qs[(ty * 4 + i) * 64 + d];
            #pragma unroll
            for (int dd = 0; dd < 4; dd++)
                kb[dd] = *(const float4*)&Kts[(d + dd) * KT_STRIDE + tx * 4];
            #pragma unroll
            for (int i = 0; i < 4; i++) {
                s[i][0] += qa[i].x * kb[0].x + qa[i].y * kb[1].x + qa[i].z * kb[2].x + qa[i].w * kb[3].x;
                s[i][1] += qa[i].x * kb[0].y + qa[i].y * kb[1].y + qa[i].z * kb[2].y + qa[i].w * kb[3].y;
                s[i][2] += qa[i].x * kb[0].z + qa[i].y * kb[1].z + qa[i].z * kb[2].z + qa[i].w * kb[3].z;
                s[i][3] += qa[i].x * kb[0].w + qa[i].y * kb[1].w + qa[i].z * kb[2].w + qa[i].w * kb[3].w;
            }
        }

        // Scale + mask (replacement, matching reference where())
        int mk[4];
        #pragma unroll
        for (int j = 0; j < 4; j++) mk[j] = ms[tx * 4 + j];
        #pragma unroll
        for (int i = 0; i < 4; i++)
            #pragma unroll
            for (int j = 0; j < 4; j++)
                s[i][j] = mk[j] ? (s[i][j] * scale) : -1e9f;

        // Online softmax per row group
        #pragma unroll
        for (int i = 0; i < 4; i++) {
            float tm = fmaxf(fmaxf(s[i][0], s[i][1]), fmaxf(s[i][2], s[i][3]));
            #pragma unroll
            for (int off = 8; off >= 1; off >>= 1)
                tm = fmaxf(tm, __shfl_xor_sync(0xffffffffu, tm, off));
            float m_new = fmaxf(m_i[i], tm);
            float alpha = __expf(m_i[i] - m_new);  // -inf first time -> 0
            float p0 = __expf(s[i][0] - m_new);
            float p1 = __expf(s[i][1] - m_new);
            float p2 = __expf(s[i][2] - m_new);
            float p3 = __expf(s[i][3] - m_new);
            *(float4*)&Ps[(ty * 4 + i) * 64 + tx * 4] = make_float4(p0, p1, p2, p3);
            float rs = p0 + p1 + p2 + p3;
            #pragma unroll
            for (int off = 8; off >= 1; off >>= 1)
                rs += __shfl_xor_sync(0xffffffffu, rs, off);
            l_i[i] = l_i[i] * alpha + rs;
            m_i[i] = m_new;
            #pragma unroll
            for (int j = 0; j < 4; j++) o[i][j] *= alpha;
        }
        __syncthreads();  // Ps visible to all

        // O += P @ V
        for (int k = 0; k < 64; k += 4) {
            float4 pa[4], vb[4];
            #pragma unroll
            for (int i = 0; i < 4; i++)
                pa[i] = *(const float4*)&Ps[(ty * 4 + i) * 64 + k];
            #pragma unroll
            for (int kk = 0; kk < 4; kk++)
                vb[kk] = *(const float4*)&Vs[(k + kk) * 64 + tx * 4];
            #pragma unroll
            for (int i = 0; i < 4; i++) {
                o[i][0] += pa[i].x * vb[0].x + pa[i].y * vb[1].x + pa[i].z * vb[2].x + pa[i].w * vb[3].x;
                o[i][1] += pa[i].x * vb[0].y + pa[i].y * vb[1].y + pa[i].z * vb[2].y + pa[i].w * vb[3].y;
                o[i][2] += pa[i].x * vb[0].z + pa[i].y * vb[1].z + pa[i].z * vb[2].z + pa[i].w * vb[3].z;
                o[i][3] += pa[i].x * vb[0].w + pa[i].y * vb[1].w + pa[i].z * vb[2].w + pa[i].w * vb[3].w;
            }
        }
    }

    // Normalize and write out [B, L, H, dk]
    #pragma unroll
    for (int i = 0; i < 4; i++) {
        float inv = 1.0f / l_i[i];
        size_t row = (size_t)b * LDIM + q0 + ty * 4 + i;
        float4 v = make_float4(o[i][0] * inv, o[i][1] * inv, o[i][2] * inv, o[i][3] * inv);
        *(float4*)&out[row * DMODEL + h * DKH + tx * 4] = v;
    }
}

// ---------------------------------------------------------------------------
// Launch
// ---------------------------------------------------------------------------
extern "C" void kernel_launch(void* const* d_in, const int* in_sizes, int n_in,
                              void* d_out, int out_size)
{
    const float* x     = (const float*)d_in[0];
    const int*   mask  = (const int*)  d_in[1];
    const float* Wqkv  = (const float*)d_in[2];
    const float* bqkv  = (const float*)d_in[3];
    const float* Wout  = (const float*)d_in[4];
    const float* bout  = (const float*)d_in[5];
    float* out = (float*)d_out;

    float *qkv = nullptr, *attn = nullptr;
    cudaGetSymbolAddress((void**)&qkv,  g_qkv);
    cudaGetSymbolAddress((void**)&attn, g_attn);

    cudaFuncSetAttribute(attn_kernel,
                         cudaFuncAttributeMaxDynamicSharedMemorySize,
                         ATTN_SMEM_BYTES);

    // 1) QKV projection: [4096,1024] @ [1024,3072] + b
    sgemm_bias_kernel<<<dim3(D3 / 128, ROWS / 128), 256>>>(
        x, Wqkv, bqkv, qkv, ROWS, D3, DMODEL);

    // 2) Fused masked attention -> [B,L,H,dk]
    attn_kernel<<<dim3(LDIM / BQ, BDIM * HEADS), 256, ATTN_SMEM_BYTES>>>(
        qkv, mask, attn);

    // 3) Output projection: [4096,1024] @ [1024,1024] + b
    sgemm_bias_kernel<<<dim3(DMODEL / 128, ROWS / 128), 256>>>(
        attn, Wout, bout, out, ROWS, DMODEL, DMODEL);
}

// round 3
// speedup vs baseline: 1.4865x; 1.4865x over previous
#include <cuda_runtime.h>
#include <math.h>
#include <stdint.h>

// Problem constants
#define BDIM   2
#define LDIM   2048
#define DMODEL 1024
#define HEADS  16
#define DKH    64
#define D3     (3 * DMODEL)
#define ROWS   (BDIM * LDIM)   // 4096
#define GK     1024            // K for both projection GEMMs

// Scratch (allocation-free: __device__ globals)
__device__ float g_qkv[(size_t)ROWS * D3];       // [B*L, 3*D]
__device__ float g_attn[(size_t)ROWS * DMODEL];  // [B,L,H,dk] (tf32-rounded)
__device__ float g_x[(size_t)ROWS * DMODEL];     // tf32-rounded x
__device__ float g_wqkvT[(size_t)D3 * GK];       // [3072][1024] k-major, tf32-rounded
__device__ float g_woutT[(size_t)DMODEL * GK];   // [1024][1024] k-major, tf32-rounded

// ===========================================================================
// Helpers
// ===========================================================================
__device__ __forceinline__ float tf32r(float x) {
    uint32_t y;
    asm("cvt.rna.tf32.f32 %0, %1;" : "=r"(y) : "f"(x));
    return __uint_as_float(y);
}
__device__ __forceinline__ uint32_t smem_u32(const void* p) {
    uint32_t a;
    asm("{ .reg .u64 t; cvta.to.shared.u64 t, %1; cvt.u32.u64 %0, t; }" : "=r"(a) : "l"(p));
    return a;
}
#define SWZ128(x) ((x) ^ (((x) >> 3) & 0x70))

__device__ __forceinline__ void cp16(uint32_t dst, const void* src) {
    asm volatile("cp.async.cg.shared.global [%0], [%1], 16;" :: "r"(dst), "l"(src));
}
__device__ __forceinline__ void ldsm4(uint32_t& r0, uint32_t& r1, uint32_t& r2, uint32_t& r3,
                                      uint32_t addr) {
    asm volatile("ldmatrix.sync.aligned.m8n8.x4.shared.b16 {%0,%1,%2,%3}, [%4];"
                 : "=r"(r0), "=r"(r1), "=r"(r2), "=r"(r3) : "r"(addr));
}
__device__ __forceinline__ void mma_tf32(float* c, const uint32_t* a, uint32_t b0, uint32_t b1) {
    asm volatile("mma.sync.aligned.m16n8k8.row.col.f32.tf32.tf32.f32 "
                 "{%0,%1,%2,%3}, {%4,%5,%6,%7}, {%8,%9}, {%0,%1,%2,%3};"
                 : "+f"(c[0]), "+f"(c[1]), "+f"(c[2]), "+f"(c[3])
                 : "r"(a[0]), "r"(a[1]), "r"(a[2]), "r"(a[3]), "r"(b0), "r"(b1));
}

// ===========================================================================
// Prep kernels
// ===========================================================================
__global__ void round_tf32_kernel(const float* __restrict__ in, float* __restrict__ out, int n4) {
    int i = blockIdx.x * blockDim.x + threadIdx.x;
    if (i < n4) {
        float4 v = ((const float4*)in)[i];
        v.x = tf32r(v.x); v.y = tf32r(v.y); v.z = tf32r(v.z); v.w = tf32r(v.w);
        ((float4*)out)[i] = v;
    }
}

// in [K][N] row-major -> out [N][K] row-major, tf32-rounded. block (32,8)
__global__ void transpose_tf32_kernel(const float* __restrict__ in, float* __restrict__ out,
                                      int K, int N) {
    __shared__ float t[32][33];
    int n0 = blockIdx.x * 32, k0 = blockIdx.y * 32;
    for (int j = threadIdx.y; j < 32; j += 8)
        t[j][threadIdx.x] = tf32r(in[(size_t)(k0 + j) * N + n0 + threadIdx.x]);
    __syncthreads();
    for (int j = threadIdx.y; j < 32; j += 8)
        out[(size_t)(n0 + j) * K + k0 + threadIdx.x] = t[threadIdx.x][j];
}

// ===========================================================================
// tf32 mma.sync GEMM: C[M,N] = A[M,K] @ Bt[N,K]^T + bias[N]
// BM=128, BN=128, BK=32, 256 threads, 2-stage cp.async pipeline.
// A and Bt are k-major with K=1024; both pre-rounded to tf32 values.
// ===========================================================================
#define GBK    32
#define GTILE  (128 * GBK * 4)          // 16KB per operand tile
#define GS_TOTAL (4 * GTILE)            // 64KB (2 stages x (A+B))

__device__ __forceinline__ void gemm_load_tile(const float* __restrict__ src, int row0, int k0,
                                               uint32_t smemBase, int tid) {
    #pragma unroll
    for (int j = 0; j < 4; j++) {
        int i   = tid + j * 256;        // 0..1023
        int row = i >> 3;               // 0..127
        int c   = i & 7;                // 16B chunk
        cp16(smemBase + SWZ128(row * 128 + c * 16),
             src + (size_t)(row0 + row) * GK + k0 + c * 4);
    }
}

__global__ __launch_bounds__(256) void gemm_mma_kernel(
    const float* __restrict__ A, const float* __restrict__ Bt,
    const float* __restrict__ bias, float* __restrict__ C, int N)
{
    extern __shared__ char smc[];
    const uint32_t sb = smem_u32(smc);
    const int tid  = threadIdx.x;
    const int lane = tid & 31;
    const int w    = tid >> 5;
    const int m0   = blockIdx.y * 128;
    const int n0   = blockIdx.x * 128;
    const int wm   = (w & 1) * 64;
    const int wn   = (w >> 1) * 32;

    // per-lane ldmatrix offsets (bytes, pre-swizzle)
    const int aOff = (wm + (lane & 15)) * 128 + ((lane >> 4) << 4);
    const int bOff = (wn + ((lane >> 4) << 3) + (lane & 7)) * 128 + (((lane >> 3) & 1) << 4);

    // smem stage bases: [A0 | B0 | A1 | B1]
    const uint32_t sA[2] = { sb, sb + 2 * GTILE };
    const uint32_t sB[2] = { sb + GTILE, sb + 3 * GTILE };

    float acc[16][4];
    #pragma unroll
    for (int t = 0; t < 16; t++)
        #pragma unroll
        for (int j = 0; j < 4; j++) acc[t][j] = 0.0f;

    gemm_load_tile(A,  m0, 0, sA[0], tid);
    gemm_load_tile(Bt, n0, 0, sB[0], tid);
    asm volatile("cp.async.commit_group;" ::: "memory");

    const int NCHUNK = GK / GBK;   // 32
    for (int c = 0; c < NCHUNK; c++) {
        if (c + 1 < NCHUNK) {
            gemm_load_tile(A,  m0, (c + 1) * GBK, sA[(c + 1) & 1], tid);
            gemm_load_tile(Bt, n0, (c + 1) * GBK, sB[(c + 1) & 1], tid);
            asm volatile("cp.async.commit_group;" ::: "memory");
            asm volatile("cp.async.wait_group 1;" ::: "memory");
        } else {
            asm volatile("cp.async.wait_group 0;" ::: "memory");
        }
        __syncthreads();

        const uint32_t ba = sA[c & 1];
        const uint32_t bb = sB[c & 1];
        #pragma unroll
        for (int ks = 0; ks < 4; ks++) {
            uint32_t a[4][4], b[2][4];
            #pragma unroll
            for (int mt = 0; mt < 4; mt++)
                ldsm4(a[mt][0], a[mt][1], a[mt][2], a[mt][3],
                      ba + SWZ128(aOff + mt * 2048 + ks * 32));
            #pragma unroll
            for (int np = 0; np < 2; np++)
                ldsm4(b[np][0], b[np][1], b[np][2], b[np][3],
                      bb + SWZ128(bOff + np * 2048 + ks * 32));
            #pragma unroll
            for (int mt = 0; mt < 4; mt++)
                #pragma unroll
                for (int nt = 0; nt < 4; nt++)
                    mma_tf32(acc[mt * 4 + nt], a[mt],
                             b[nt >> 1][(nt & 1) * 2], b[nt >> 1][(nt & 1) * 2 + 1]);
        }
        __syncthreads();
    }

    // Epilogue: c-frag (row=lane/4 [+8], col=(lane%4)*2 [+1]) + bias
    #pragma unroll
    for (int mt = 0; mt < 4; mt++) {
        #pragma unroll
        for (int nt = 0; nt < 4; nt++) {
            const float* cc = acc[mt * 4 + nt];
            int row = m0 + wm + mt * 16 + (lane >> 2);
            int col = n0 + wn + nt * 8 + (lane & 3) * 2;
            float2 bv = *(const float2*)&bias[col];
            float2 o0 = make_float2(cc[0] + bv.x, cc[1] + bv.y);
            float2 o1 = make_float2(cc[2] + bv.x, cc[3] + bv.y);
            *(float2*)&C[(size_t)row * N + col]       = o0;
            *(float2*)&C[(size_t)(row + 8) * N + col] = o1;
        }
    }
}

// ===========================================================================
// Flash-attention style fused kernel (R1-proven; epilogue now tf32-rounds).
// ===========================================================================
#define BQ 64
#define BK 64
#define KT_STRIDE 68

#define SM_QS   0
#define SM_KT   (SM_QS + 64 * 64)
#define SM_VS   (SM_KT + 64 * KT_STRIDE)
#define SM_PS   (SM_VS + 64 * 64)
#define SM_MS   (SM_PS + 64 * 64)
#define ATTN_SMEM_BYTES ((SM_MS + 64) * 4)

__global__ __launch_bounds__(256) void attn_kernel(
    const float* __restrict__ qkv, const int* __restrict__ mask,
    float* __restrict__ out)
{
    extern __shared__ float smf[];
    float* Qs  = smf + SM_QS;
    float* Kts = smf + SM_KT;
    float* Vs  = smf + SM_VS;
    float* Ps  = smf + SM_PS;
    int*   ms  = (int*)(smf + SM_MS);

    const int tid = threadIdx.x;
    const int tx  = tid & 15;
    const int ty  = tid >> 4;
    const int bh  = blockIdx.y;
    const int b   = bh >> 4;
    const int h   = bh & 15;
    const int q0  = blockIdx.x * BQ;
    const float scale = 0.125f;

    const size_t base = (size_t)b * LDIM * D3 + (size_t)h * DKH;

    for (int i = tid; i < 64 * 16; i += 256) {
        int r  = i >> 4;
        int d4 = (i & 15) * 4;
        float4 v = *(const float4*)&qkv[base + (size_t)(q0 + r) * D3 + d4];
        *(float4*)&Qs[r * 64 + d4] = v;
    }

    float m_i[4], l_i[4], o[4][4];
    #pragma unroll
    for (int i = 0; i < 4; i++) {
        m_i[i] = -INFINITY;
        l_i[i] = 0.0f;
        #pragma unroll
        for (int j = 0; j < 4; j++) o[i][j] = 0.0f;
    }

    for (int k0 = 0; k0 < LDIM; k0 += BK) {
        __syncthreads();

        for (int i = tid; i < 64 * 16; i += 256) {
            int c  = i >> 4;
            int d4 = (i & 15) * 4;
            float4 kv = *(const float4*)&qkv[base + (size_t)(k0 + c) * D3 + DMODEL + d4];
            Kts[(d4 + 0) * KT_STRIDE + c] = kv.x;
            Kts[(d4 + 1) * KT_STRIDE + c] = kv.y;
            Kts[(d4 + 2) * KT_STRIDE + c] = kv.z;
            Kts[(d4 + 3) * KT_STRIDE + c] = kv.w;
            float4 vv = *(const float4*)&qkv[base + (size_t)(k0 + c) * D3 + 2 * DMODEL + d4];
            *(float4*)&Vs[c * 64 + d4] = vv;
        }
        if (tid < 64) ms[tid] = mask[b * LDIM + k0 + tid];
        __syncthreads();

        float s[4][4];
        #pragma unroll
        for (int i = 0; i < 4; i++)
            #pragma unroll
            for (int j = 0; j < 4; j++) s[i][j] = 0.0f;

        for (int d = 0; d < 64; d += 4) {
            float4 qa[4], kb[4];
            #pragma unroll
            for (int i = 0; i < 4; i++)
                qa[i] = *(const float4*)&Qs[(ty * 4 + i) * 64 + d];
            #pragma unroll
            for (int dd = 0; dd < 4; dd++)
                kb[dd] = *(const float4*)&Kts[(d + dd) * KT_STRIDE + tx * 4];
            #pragma unroll
            for (int i = 0; i < 4; i++) {
                s[i][0] += qa[i].x * kb[0].x + qa[i].y * kb[1].x + qa[i].z * kb[2].x + qa[i].w * kb[3].x;
                s[i][1] += qa[i].x * kb[0].y + qa[i].y * kb[1].y + qa[i].z * kb[2].y + qa[i].w * kb[3].y;
                s[i][2] += qa[i].x * kb[0].z + qa[i].y * kb[1].z + qa[i].z * kb[2].z + qa[i].w * kb[3].z;
                s[i][3] += qa[i].x * kb[0].w + qa[i].y * kb[1].w + qa[i].z * kb[2].w + qa[i].w * kb[3].w;
            }
        }

        int mk[4];
        #pragma unroll
        for (int j = 0; j < 4; j++) mk[j] = ms[tx * 4 + j];
        #pragma unroll
        for (int i = 0; i < 4; i++)
            #pragma unroll
            for (int j = 0; j < 4; j++)
                s[i][j] = mk[j] ? (s[i][j] * scale) : -1e9f;

        #pragma unroll
        for (int i = 0; i < 4; i++) {
            float tm = fmaxf(fmaxf(s[i][0], s[i][1]), fmaxf(s[i][2], s[i][3]));
            #pragma unroll
            for (int off = 8; off >= 1; off >>= 1)
                tm = fmaxf(tm, __shfl_xor_sync(0xffffffffu, tm, off));
            float m_new = fmaxf(m_i[i], tm);
            float alpha = __expf(m_i[i] - m_new);
            float p0 = __expf(s[i][0] - m_new);
            float p1 = __expf(s[i][1] - m_new);
            float p2 = __expf(s[i][2] - m_new);
            float p3 = __expf(s[i][3] - m_new);
            *(float4*)&Ps[(ty * 4 + i) * 64 + tx * 4] = make_float4(p0, p1, p2, p3);
            float rs = p0 + p1 + p2 + p3;
            #pragma unroll
            for (int off = 8; off >= 1; off >>= 1)
                rs += __shfl_xor_sync(0xffffffffu, rs, off);
            l_i[i] = l_i[i] * alpha + rs;
            m_i[i] = m_new;
            #pragma unroll
            for (int j = 0; j < 4; j++) o[i][j] *= alpha;
        }
        __syncthreads();

        for (int k = 0; k < 64; k += 4) {
            float4 pa[4], vb[4];
            #pragma unroll
            for (int i = 0; i < 4; i++)
                pa[i] = *(const float4*)&Ps[(ty * 4 + i) * 64 + k];
            #pragma unroll
            for (int kk = 0; kk < 4; kk++)
                vb[kk] = *(const float4*)&Vs[(k + kk) * 64 + tx * 4];
            #pragma unroll
            for (int i = 0; i < 4; i++) {
                o[i][0] += pa[i].x * vb[0].x + pa[i].y * vb[1].x + pa[i].z * vb[2].x + pa[i].w * vb[3].x;
                o[i][1] += pa[i].x * vb[0].y + pa[i].y * vb[1].y + pa[i].z * vb[2].y + pa[i].w * vb[3].y;
                o[i][2] += pa[i].x * vb[0].z + pa[i].y * vb[1].z + pa[i].z * vb[2].z + pa[i].w * vb[3].z;
                o[i][3] += pa[i].x * vb[0].w + pa[i].y * vb[1].w + pa[i].z * vb[2].w + pa[i].w * vb[3].w;
            }
        }
    }

    #pragma unroll
    for (int i = 0; i < 4; i++) {
        float inv = 1.0f / l_i[i];
        size_t row = (size_t)b * LDIM + q0 + ty * 4 + i;
        float4 v = make_float4(tf32r(o[i][0] * inv), tf32r(o[i][1] * inv),
                               tf32r(o[i][2] * inv), tf32r(o[i][3] * inv));
        *(float4*)&out[row * DMODEL + h * DKH + tx * 4] = v;
    }
}

// ---------------------------------------------------------------------------
// Launch
// ---------------------------------------------------------------------------
extern "C" void kernel_launch(void* const* d_in, const int* in_sizes, int n_in,
                              void* d_out, int out_size)
{
    const float* x     = (const float*)d_in[0];
    const int*   mask  = (const int*)  d_in[1];
    const float* Wqkv  = (const float*)d_in[2];
    const float* bqkv  = (const float*)d_in[3];
    const float* Wout  = (const float*)d_in[4];
    const float* bout  = (const float*)d_in[5];
    float* out = (float*)d_out;

    float *qkv, *attn, *xr, *wqkvT, *woutT;
    cudaGetSymbolAddress((void**)&qkv,   g_qkv);
    cudaGetSymbolAddress((void**)&attn,  g_attn);
    cudaGetSymbolAddress((void**)&xr,    g_x);
    cudaGetSymbolAddress((void**)&wqkvT, g_wqkvT);
    cudaGetSymbolAddress((void**)&woutT, g_woutT);

    cudaFuncSetAttribute(gemm_mma_kernel,
                         cudaFuncAttributeMaxDynamicSharedMemorySize, GS_TOTAL);
    cudaFuncSetAttribute(attn_kernel,
                         cudaFuncAttributeMaxDynamicSharedMemorySize, ATTN_SMEM_BYTES);

    // Prep: tf32-round x; transpose+round weights to [N][K]
    round_tf32_kernel<<<(ROWS * DMODEL / 4 + 255) / 256, 256>>>(x, xr, ROWS * DMODEL / 4);
    transpose_tf32_kernel<<<dim3(D3 / 32, GK / 32), dim3(32, 8)>>>(Wqkv, wqkvT, GK, D3);
    transpose_tf32_kernel<<<dim3(DMODEL / 32, GK / 32), dim3(32, 8)>>>(Wout, woutT, GK, DMODEL);

    // 1) QKV projection: [4096,1024] @ [1024,3072] + b   (mma.sync tf32)
    gemm_mma_kernel<<<dim3(D3 / 128, ROWS / 128), 256, GS_TOTAL>>>(
        xr, wqkvT, bqkv, qkv, D3);

    // 2) Fused masked attention -> [B,L,H,dk] (tf32-rounded output)
    attn_kernel<<<dim3(LDIM / BQ, BDIM * HEADS), 256, ATTN_SMEM_BYTES>>>(
        qkv, mask, attn);

    // 3) Output projection: [4096,1024] @ [1024,1024] + b   (mma.sync tf32)
    gemm_mma_kernel<<<dim3(DMODEL / 128, ROWS / 128), 256, GS_TOTAL>>>(
        attn, woutT, bout, out, DMODEL);
}

// round 4
// speedup vs baseline: 3.2949x; 2.2165x over previous
#include <cuda_runtime.h>
#include <math.h>
#include <stdint.h>

// Problem constants
#define BDIM   2
#define LDIM   2048
#define DMODEL 1024
#define HEADS  16
#define DKH    64
#define D3     (3 * DMODEL)
#define ROWS   (BDIM * LDIM)   // 4096
#define GK     1024            // K for both projection GEMMs

// Scratch (allocation-free: __device__ globals)
__device__ float g_qkv[(size_t)ROWS * D3];       // [B*L, 3*D]
__device__ float g_attn[(size_t)ROWS * DMODEL];  // [B,L,H,dk] (tf32-rounded)
__device__ float g_x[(size_t)ROWS * DMODEL];     // tf32-rounded x
__device__ float g_wqkvT[(size_t)D3 * GK];       // [3072][1024] k-major, tf32-rounded
__device__ float g_woutT[(size_t)DMODEL * GK];   // [1024][1024] k-major, tf32-rounded

// ===========================================================================
// Helpers
// ===========================================================================
__device__ __forceinline__ float tf32r(float x) {
    uint32_t y;
    asm("cvt.rna.tf32.f32 %0, %1;" : "=r"(y) : "f"(x));
    return __uint_as_float(y);
}
__device__ __forceinline__ uint32_t smem_u32(const void* p) {
    uint32_t a;
    asm("{ .reg .u64 t; cvta.to.shared.u64 t, %1; cvt.u32.u64 %0, t; }" : "=r"(a) : "l"(p));
    return a;
}
#define SWZ128(x) ((x) ^ (((x) >> 3) & 0x70))

__device__ __forceinline__ void cp16(uint32_t dst, const void* src) {
    asm volatile("cp.async.cg.shared.global [%0], [%1], 16;" :: "r"(dst), "l"(src));
}
__device__ __forceinline__ void ldsm4(uint32_t& r0, uint32_t& r1, uint32_t& r2, uint32_t& r3,
                                      uint32_t addr) {
    asm volatile("ldmatrix.sync.aligned.m8n8.x4.shared.b16 {%0,%1,%2,%3}, [%4];"
                 : "=r"(r0), "=r"(r1), "=r"(r2), "=r"(r3) : "r"(addr));
}
__device__ __forceinline__ void mma_tf32(float* c, const uint32_t* a, uint32_t b0, uint32_t b1) {
    asm volatile("mma.sync.aligned.m16n8k8.row.col.f32.tf32.tf32.f32 "
                 "{%0,%1,%2,%3}, {%4,%5,%6,%7}, {%8,%9}, {%0,%1,%2,%3};"
                 : "+f"(c[0]), "+f"(c[1]), "+f"(c[2]), "+f"(c[3])
                 : "r"(a[0]), "r"(a[1]), "r"(a[2]), "r"(a[3]), "r"(b0), "r"(b1));
}

// ===========================================================================
// Prep kernels
// ===========================================================================
__global__ void round_tf32_kernel(const float* __restrict__ in, float* __restrict__ out, int n4) {
    int i = blockIdx.x * blockDim.x + threadIdx.x;
    if (i < n4) {
        float4 v = ((const float4*)in)[i];
        v.x = tf32r(v.x); v.y = tf32r(v.y); v.z = tf32r(v.z); v.w = tf32r(v.w);
        ((float4*)out)[i] = v;
    }
}

// in [K][N] row-major -> out [N][K] row-major, tf32-rounded. block (32,8)
__global__ void transpose_tf32_kernel(const float* __restrict__ in, float* __restrict__ out,
                                      int K, int N) {
    __shared__ float t[32][33];
    int n0 = blockIdx.x * 32, k0 = blockIdx.y * 32;
    for (int j = threadIdx.y; j < 32; j += 8)
        t[j][threadIdx.x] = tf32r(in[(size_t)(k0 + j) * N + n0 + threadIdx.x]);
    __syncthreads();
    for (int j = threadIdx.y; j < 32; j += 8)
        out[(size_t)(n0 + j) * K + k0 + threadIdx.x] = t[threadIdx.x][j];
}

// ===========================================================================
// tf32 mma.sync GEMM: C[M,N] = A[M,K] @ Bt[N,K]^T + bias[N]  (R3-validated)
// ===========================================================================
#define GBK    32
#define GTILE  (128 * GBK * 4)
#define GS_TOTAL (4 * GTILE)

__device__ __forceinline__ void gemm_load_tile(const float* __restrict__ src, int row0, int k0,
                                               uint32_t smemBase, int tid) {
    #pragma unroll
    for (int j = 0; j < 4; j++) {
        int i   = tid + j * 256;
        int row = i >> 3;
        int c   = i & 7;
        cp16(smemBase + SWZ128(row * 128 + c * 16),
             src + (size_t)(row0 + row) * GK + k0 + c * 4);
    }
}

__global__ __launch_bounds__(256) void gemm_mma_kernel(
    const float* __restrict__ A, const float* __restrict__ Bt,
    const float* __restrict__ bias, float* __restrict__ C, int N)
{
    extern __shared__ char smc[];
    const uint32_t sb = smem_u32(smc);
    const int tid  = threadIdx.x;
    const int lane = tid & 31;
    const int w    = tid >> 5;
    const int m0   = blockIdx.y * 128;
    const int n0   = blockIdx.x * 128;
    const int wm   = (w & 1) * 64;
    const int wn   = (w >> 1) * 32;

    const int aOff = (wm + (lane & 15)) * 128 + ((lane >> 4) << 4);
    const int bOff = (wn + ((lane >> 4) << 3) + (lane & 7)) * 128 + (((lane >> 3) & 1) << 4);

    const uint32_t sA[2] = { sb, sb + 2 * GTILE };
    const uint32_t sB[2] = { sb + GTILE, sb + 3 * GTILE };

    float acc[16][4];
    #pragma unroll
    for (int t = 0; t < 16; t++)
        #pragma unroll
        for (int j = 0; j < 4; j++) acc[t][j] = 0.0f;

    gemm_load_tile(A,  m0, 0, sA[0], tid);
    gemm_load_tile(Bt, n0, 0, sB[0], tid);
    asm volatile("cp.async.commit_group;" ::: "memory");

    const int NCHUNK = GK / GBK;
    for (int c = 0; c < NCHUNK; c++) {
        if (c + 1 < NCHUNK) {
            gemm_load_tile(A,  m0, (c + 1) * GBK, sA[(c + 1) & 1], tid);
            gemm_load_tile(Bt, n0, (c + 1) * GBK, sB[(c + 1) & 1], tid);
            asm volatile("cp.async.commit_group;" ::: "memory");
            asm volatile("cp.async.wait_group 1;" ::: "memory");
        } else {
            asm volatile("cp.async.wait_group 0;" ::: "memory");
        }
        __syncthreads();

        const uint32_t ba = sA[c & 1];
        const uint32_t bb = sB[c & 1];
        #pragma unroll
        for (int ks = 0; ks < 4; ks++) {
            uint32_t a[4][4], b[2][4];
            #pragma unroll
            for (int mt = 0; mt < 4; mt++)
                ldsm4(a[mt][0], a[mt][1], a[mt][2], a[mt][3],
                      ba + SWZ128(aOff + mt * 2048 + ks * 32));
            #pragma unroll
            for (int np = 0; np < 2; np++)
                ldsm4(b[np][0], b[np][1], b[np][2], b[np][3],
                      bb + SWZ128(bOff + np * 2048 + ks * 32));
            #pragma unroll
            for (int mt = 0; mt < 4; mt++)
                #pragma unroll
                for (int nt = 0; nt < 4; nt++)
                    mma_tf32(acc[mt * 4 + nt], a[mt],
                             b[nt >> 1][(nt & 1) * 2], b[nt >> 1][(nt & 1) * 2 + 1]);
        }
        __syncthreads();
    }

    #pragma unroll
    for (int mt = 0; mt < 4; mt++) {
        #pragma unroll
        for (int nt = 0; nt < 4; nt++) {
            const float* cc = acc[mt * 4 + nt];
            int row = m0 + wm + mt * 16 + (lane >> 2);
            int col = n0 + wn + nt * 8 + (lane & 3) * 2;
            float2 bv = *(const float2*)&bias[col];
            float2 o0 = make_float2(cc[0] + bv.x, cc[1] + bv.y);
            float2 o1 = make_float2(cc[2] + bv.x, cc[3] + bv.y);
            *(float2*)&C[(size_t)row * N + col]       = o0;
            *(float2*)&C[(size_t)(row + 8) * N + col] = o1;
        }
    }
}

// ===========================================================================
// Tensor-core flash attention (mma.sync tf32).
// Grid: (L/128, B*H). 256 threads = 8 warps x 16 q-rows. KV tiles of 64.
// qkv layout [B, L, 3, H, 64]; out [B, L, H, 64] (tf32-rounded for GEMM3).
// ===========================================================================
#define ABQ 128
#define ABK 64
#define AST 68                       // padded row stride (floats): 68 % 32 = 4
#define AQS 0
#define AKS (ABQ * AST)              // 8704
#define AVS (AKS + ABK * AST)        // 13056
#define AMS (AVS + ABK * AST)        // 17408 (ints)
#define ATTN_SM_BYTES ((AMS + ABK) * 4)

__global__ void __launch_bounds__(256, 2) attn_mma_kernel(
    const float* __restrict__ qkv, const int* __restrict__ mask,
    float* __restrict__ out)
{
    extern __shared__ float smf[];
    float* Qs = smf + AQS;
    float* Ks = smf + AKS;
    float* Vs = smf + AVS;
    int*   ms = (int*)(smf + AMS);

    const int tid  = threadIdx.x;
    const int lane = tid & 31;
    const int w    = tid >> 5;
    const int g    = lane >> 2;      // group row
    const int q    = lane & 3;       // thread-in-group
    const int b    = blockIdx.y >> 4;
    const int h    = blockIdx.y & 15;
    const int q0   = blockIdx.x * ABQ;
    const int wq0  = w * 16;

    const size_t base = (size_t)b * LDIM * D3 + (size_t)h * DKH;

    // Load Q tile [128 x 64], tf32-rounded
    for (int i = tid; i < ABQ * 16; i += 256) {
        int r = i >> 4, d4 = (i & 15) * 4;
        float4 v = *(const float4*)&qkv[base + (size_t)(q0 + r) * D3 + d4];
        v.x = tf32r(v.x); v.y = tf32r(v.y); v.z = tf32r(v.z); v.w = tf32r(v.w);
        *(float4*)&Qs[r * AST + d4] = v;
    }

    float O[8][4];
    #pragma unroll
    for (int t = 0; t < 8; t++)
        #pragma unroll
        for (int j = 0; j < 4; j++) O[t][j] = 0.0f;
    float m0 = -INFINITY, m1 = -INFINITY, l0 = 0.0f, l1 = 0.0f;

    const uint32_t sb = smem_u32(smf);
    const uint32_t aAddr  = sb + (AQS + (wq0 + (lane & 15)) * AST) * 4 + ((lane >> 4) << 4);
    const uint32_t bAddrK = sb + (AKS + (((lane >> 4) << 3) + (lane & 7)) * AST) * 4
                               + (((lane >> 3) & 1) << 4);

    for (int k0 = 0; k0 < LDIM; k0 += ABK) {
        __syncthreads();
        // Load K, V tiles [64 x 64] (tf32-rounded) + mask
        for (int i = tid; i < ABK * 16; i += 256) {
            int r = i >> 4, d4 = (i & 15) * 4;
            const float* src = &qkv[base + (size_t)(k0 + r) * D3 + DMODEL + d4];
            float4 kv4 = *(const float4*)src;
            kv4.x = tf32r(kv4.x); kv4.y = tf32r(kv4.y);
            kv4.z = tf32r(kv4.z); kv4.w = tf32r(kv4.w);
            *(float4*)&Ks[r * AST + d4] = kv4;
            float4 vv = *(const float4*)(src + DMODEL);
            vv.x = tf32r(vv.x); vv.y = tf32r(vv.y);
            vv.z = tf32r(vv.z); vv.w = tf32r(vv.w);
            *(float4*)&Vs[r * AST + d4] = vv;
        }
        if (tid < ABK) ms[tid] = mask[b * LDIM + k0 + tid];
        __syncthreads();

        // ---- S = Q K^T  (16 rows x 64 cols per warp) ----
        float S[8][4];
        #pragma unroll
        for (int t = 0; t < 8; t++)
            #pragma unroll
            for (int j = 0; j < 4; j++) S[t][j] = 0.0f;

        #pragma unroll
        for (int ks = 0; ks < 8; ks++) {
            uint32_t av[4];
            ldsm4(av[0], av[1], av[2], av[3], aAddr + ks * 32);
            #pragma unroll
            for (int ntp = 0; ntp < 4; ntp++) {
                uint32_t b0, b1, b2, b3;
                ldsm4(b0, b1, b2, b3, bAddrK + ntp * 16 * AST * 4 + ks * 32);
                mma_tf32(S[2 * ntp],     av, b0, b1);
                mma_tf32(S[2 * ntp + 1], av, b2, b3);
            }
        }

        // ---- mask + scale ----
        #pragma unroll
        for (int nt = 0; nt < 8; nt++) {
            int2 mk = *(const int2*)&ms[nt * 8 + 2 * q];
            S[nt][0] = mk.x ? S[nt][0] * 0.125f : -1e9f;
            S[nt][1] = mk.y ? S[nt][1] * 0.125f : -1e9f;
            S[nt][2] = mk.x ? S[nt][2] * 0.125f : -1e9f;
            S[nt][3] = mk.y ? S[nt][3] * 0.125f : -1e9f;
        }

        // ---- online softmax (rows g and g+8) ----
        float mx0 = -3e38f, mx1 = -3e38f;
        #pragma unroll
        for (int nt = 0; nt < 8; nt++) {
            mx0 = fmaxf(mx0, fmaxf(S[nt][0], S[nt][1]));
            mx1 = fmaxf(mx1, fmaxf(S[nt][2], S[nt][3]));
        }
        mx0 = fmaxf(mx0, __shfl_xor_sync(0xffffffffu, mx0, 1));
        mx0 = fmaxf(mx0, __shfl_xor_sync(0xffffffffu, mx0, 2));
        mx1 = fmaxf(mx1, __shfl_xor_sync(0xffffffffu, mx1, 1));
        mx1 = fmaxf(mx1, __shfl_xor_sync(0xffffffffu, mx1, 2));
        float mn0 = fmaxf(m0, mx0), mn1 = fmaxf(m1, mx1);
        float al0 = __expf(m0 - mn0), al1 = __expf(m1 - mn1);
        m0 = mn0; m1 = mn1;

        float s0 = 0.0f, s1 = 0.0f;
        #pragma unroll
        for (int nt = 0; nt < 8; nt++) {
            S[nt][0] = __expf(S[nt][0] - mn0); s0 += S[nt][0];
            S[nt][1] = __expf(S[nt][1] - mn0); s0 += S[nt][1];
            S[nt][2] = __expf(S[nt][2] - mn1); s1 += S[nt][2];
            S[nt][3] = __expf(S[nt][3] - mn1); s1 += S[nt][3];
        }
        s0 += __shfl_xor_sync(0xffffffffu, s0, 1);
        s0 += __shfl_xor_sync(0xffffffffu, s0, 2);
        s1 += __shfl_xor_sync(0xffffffffu, s1, 1);
        s1 += __shfl_xor_sync(0xffffffffu, s1, 2);
        l0 = l0 * al0 + s0;
        l1 = l1 * al1 + s1;
        #pragma unroll
        for (int t = 0; t < 8; t++) {
            O[t][0] *= al0; O[t][1] *= al0;
            O[t][2] *= al1; O[t][3] *= al1;
        }

        // ---- O += P V  (P c-frag -> a-frag via quad shuffles) ----
        const int srcb = lane & ~3;
        const int sl0  = srcb | (q >> 1);
        const int sl1  = sl0 + 2;
        #pragma unroll
        for (int j = 0; j < 8; j++) {
            float x00 = __shfl_sync(0xffffffffu, S[j][0], sl0);
            float x01 = __shfl_sync(0xffffffffu, S[j][1], sl0);
            float x02 = __shfl_sync(0xffffffffu, S[j][2], sl0);
            float x03 = __shfl_sync(0xffffffffu, S[j][3], sl0);
            float x10 = __shfl_sync(0xffffffffu, S[j][0], sl1);
            float x11 = __shfl_sync(0xffffffffu, S[j][1], sl1);
            float x12 = __shfl_sync(0xffffffffu, S[j][2], sl1);
            float x13 = __shfl_sync(0xffffffffu, S[j][3], sl1);
            uint32_t pa[4];
            pa[0] = __float_as_uint(tf32r((q & 1) ? x01 : x00));
            pa[1] = __float_as_uint(tf32r((q & 1) ? x03 : x02));
            pa[2] = __float_as_uint(tf32r((q & 1) ? x11 : x10));
            pa[3] = __float_as_uint(tf32r((q & 1) ? x13 : x12));

            const float* vr0 = &Vs[(j * 8 + q) * AST + g];
            const float* vr1 = vr0 + 4 * AST;
            #pragma unroll
            for (int nt = 0; nt < 8; nt++) {
                uint32_t b0 = __float_as_uint(vr0[nt * 8]);
                uint32_t b1 = __float_as_uint(vr1[nt * 8]);
                mma_tf32(O[nt], pa, b0, b1);
            }
        }
    }

    // ---- epilogue: O/l, tf32-rounded, to [B,L,H,64] ----
    float il0 = 1.0f / l0, il1 = 1.0f / l1;
    int row0 = q0 + wq0 + g;
    size_t o0 = ((size_t)(b * LDIM + row0)) * DMODEL + h * DKH;
    #pragma unroll
    for (int nt = 0; nt < 8; nt++) {
        int col = nt * 8 + 2 * q;
        float2 v0 = make_float2(tf32r(O[nt][0] * il0), tf32r(O[nt][1] * il0));
        float2 v1 = make_float2(tf32r(O[nt][2] * il1), tf32r(O[nt][3] * il1));
        *(float2*)&out[o0 + col]              = v0;
        *(float2*)&out[o0 + 8 * DMODEL + col] = v1;
    }
}

// ---------------------------------------------------------------------------
// Launch
// ---------------------------------------------------------------------------
extern "C" void kernel_launch(void* const* d_in, const int* in_sizes, int n_in,
                              void* d_out, int out_size)
{
    const float* x     = (const float*)d_in[0];
    const int*   mask  = (const int*)  d_in[1];
    const float* Wqkv  = (const float*)d_in[2];
    const float* bqkv  = (const float*)d_in[3];
    const float* Wout  = (const float*)d_in[4];
    const float* bout  = (const float*)d_in[5];
    float* out = (float*)d_out;

    float *qkv, *attn, *xr, *wqkvT, *woutT;
    cudaGetSymbolAddress((void**)&qkv,   g_qkv);
    cudaGetSymbolAddress((void**)&attn,  g_attn);
    cudaGetSymbolAddress((void**)&xr,    g_x);
    cudaGetSymbolAddress((void**)&wqkvT, g_wqkvT);
    cudaGetSymbolAddress((void**)&woutT, g_woutT);

    cudaFuncSetAttribute(gemm_mma_kernel,
                         cudaFuncAttributeMaxDynamicSharedMemorySize, GS_TOTAL);
    cudaFuncSetAttribute(attn_mma_kernel,
                         cudaFuncAttributeMaxDynamicSharedMemorySize, ATTN_SM_BYTES);

    // Prep: tf32-round x; transpose+round weights to [N][K]
    round_tf32_kernel<<<(ROWS * DMODEL / 4 + 255) / 256, 256>>>(x, xr, ROWS * DMODEL / 4);
    transpose_tf32_kernel<<<dim3(D3 / 32, GK / 32), dim3(32, 8)>>>(Wqkv, wqkvT, GK, D3);
    transpose_tf32_kernel<<<dim3(DMODEL / 32, GK / 32), dim3(32, 8)>>>(Wout, woutT, GK, DMODEL);

    // 1) QKV projection (mma.sync tf32)
    gemm_mma_kernel<<<dim3(D3 / 128, ROWS / 128), 256, GS_TOTAL>>>(
        xr, wqkvT, bqkv, qkv, D3);

    // 2) Tensor-core flash attention -> [B,L,H,dk] (tf32-rounded)
    attn_mma_kernel<<<dim3(LDIM / ABQ, BDIM * HEADS), 256, ATTN_SM_BYTES>>>(
        qkv, mask, attn);

    // 3) Output projection (mma.sync tf32)
    gemm_mma_kernel<<<dim3(DMODEL / 128, ROWS / 128), 256, GS_TOTAL>>>(
        attn, woutT, bout, out, DMODEL);
}